// round 3
// baseline (speedup 1.0000x reference)
#include <cuda_runtime.h>
#include <math.h>

#define BB 64
#define SS 2048
#define II 512
#define HH 512

#define NGB 16   // batch groups
#define NGJ 8    // j slices per group
#define BC  4    // batches per group
#define JC  64   // j per slice

// per-(group,slice) progress flags: flag = number of completed steps
__device__ int g_flag[NGB * NGJ];

__global__ void reset_kernel() {
    if (threadIdx.x < NGB * NGJ) g_flag[threadIdx.x] = 0;
}

// ---- packed fp32x2 FMA (sm_100+): d = a*b + c per 32-bit half --------------
__device__ __forceinline__ unsigned long long ffma2(
    unsigned long long a, unsigned long long b, unsigned long long c) {
    unsigned long long d;
    asm("fma.rn.f32x2 %0, %1, %2, %3;" : "=l"(d) : "l"(a), "l"(b), "l"(c));
    return d;
}
__device__ __forceinline__ int ld_acq(const int* p) {
    int v;
    asm volatile("ld.global.acquire.gpu.b32 %0, [%1];" : "=r"(v) : "l"(p));
    return v;
}
__device__ __forceinline__ void st_rel(int* p, int v) {
    asm volatile("st.global.release.gpu.b32 [%0], %1;" :: "l"(p), "r"(v) : "memory");
}

// ---------------------------------------------------------------------------
// Kernel 1: xproj GEMM with packed f32x2.  P[m][j] = sum_i X[m][i]*Wx[j][i].
// 64x64 tile, ktile 16, 256 threads, per-thread 4m x 4j via 2 packed m-pairs.
// Wx tile stored DUPLICATED in SMEM so the j operand is a natural f32x2 pair.
// ---------------------------------------------------------------------------
__global__ __launch_bounds__(256) void xproj_kernel(
    const float* __restrict__ X,
    const float* __restrict__ Wx,
    float* __restrict__ P)
{
    __shared__ float Xs[16][64];    // [k][m]
    __shared__ float Wd[16][128];   // [k][2*j] each j duplicated

    const int tid  = threadIdx.x;
    const int m0   = blockIdx.x * 64;
    const int j0   = blockIdx.y * 64;
    const int tx   = tid & 15;        // m micro index (4 rows)
    const int ty   = tid >> 4;        // j micro index (4 cols)
    const int lrow = tid >> 2;        // 0..63 row to load
    const int lk4  = (tid & 3) * 4;   // k offset to load

    const float* xg = X  + (size_t)(m0 + lrow) * II + lk4;
    const float* wg = Wx + (size_t)(j0 + lrow) * II + lk4;

    unsigned long long acc[2][4];     // [m-pair][j], each packs 2 m's
#pragma unroll
    for (int r = 0; r < 2; ++r)
#pragma unroll
        for (int c = 0; c < 4; ++c) acc[r][c] = 0ull;

    for (int kc = 0; kc < II; kc += 16) {
        float4 xa = *(const float4*)(xg + kc);
        float4 wa = *(const float4*)(wg + kc);
        __syncthreads();
        Xs[lk4 + 0][lrow] = xa.x; Xs[lk4 + 1][lrow] = xa.y;
        Xs[lk4 + 2][lrow] = xa.z; Xs[lk4 + 3][lrow] = xa.w;
        *(float2*)&Wd[lk4 + 0][2 * lrow] = make_float2(wa.x, wa.x);
        *(float2*)&Wd[lk4 + 1][2 * lrow] = make_float2(wa.y, wa.y);
        *(float2*)&Wd[lk4 + 2][2 * lrow] = make_float2(wa.z, wa.z);
        *(float2*)&Wd[lk4 + 3][2 * lrow] = make_float2(wa.w, wa.w);
        __syncthreads();
#pragma unroll
        for (int k = 0; k < 16; ++k) {
            const unsigned long long a01 = *(const unsigned long long*)&Xs[k][tx * 4];
            const unsigned long long a23 = *(const unsigned long long*)&Xs[k][tx * 4 + 2];
            const unsigned long long b0  = *(const unsigned long long*)&Wd[k][ty * 8 + 0];
            const unsigned long long b1  = *(const unsigned long long*)&Wd[k][ty * 8 + 2];
            const unsigned long long b2  = *(const unsigned long long*)&Wd[k][ty * 8 + 4];
            const unsigned long long b3  = *(const unsigned long long*)&Wd[k][ty * 8 + 6];
            acc[0][0] = ffma2(a01, b0, acc[0][0]);
            acc[0][1] = ffma2(a01, b1, acc[0][1]);
            acc[0][2] = ffma2(a01, b2, acc[0][2]);
            acc[0][3] = ffma2(a01, b3, acc[0][3]);
            acc[1][0] = ffma2(a23, b0, acc[1][0]);
            acc[1][1] = ffma2(a23, b1, acc[1][1]);
            acc[1][2] = ffma2(a23, b2, acc[1][2]);
            acc[1][3] = ffma2(a23, b3, acc[1][3]);
        }
    }

    // epilogue: unpack m-pairs into two rows each
#pragma unroll
    for (int mp = 0; mp < 2; ++mp) {
        float lo[4], hi[4];
#pragma unroll
        for (int c = 0; c < 4; ++c)
            asm("mov.b64 {%0, %1}, %2;" : "=f"(lo[c]), "=f"(hi[c]) : "l"(acc[mp][c]));
        const int m = m0 + tx * 4 + 2 * mp;
        *(float4*)(P + (size_t)m       * HH + j0 + ty * 4) = make_float4(lo[0], lo[1], lo[2], lo[3]);
        *(float4*)(P + (size_t)(m + 1) * HH + j0 + ty * 4) = make_float4(hi[0], hi[1], hi[2], hi[3]);
    }
}

// ---------------------------------------------------------------------------
// Kernel 2: persistent recurrent scan, per-warp flag pipelining + f32x2.
// Grid = 128 CTAs: cta = bg*8 + jg.  CTA (bg,jg) owns batches [bg*4,+4),
// output columns [jg*64,+64).  Wh slice (64x512) transposed in SMEM (once).
// Warp w of each CTA owns k-chunk [w*64,+64): it waits on peer slice w's
// flag, loads that h chunk from L2, stores it DUPLICATED in SMEM, computes
// its k-partial with f32x2 (j packed in pairs).  red double-buffered.
// ---------------------------------------------------------------------------
#define SCAN_SMEM (512*64*4 + 4*1024*4 + 2*2048*4)   // Whs + hsdup + red2 = 163840

__global__ __launch_bounds__(256, 1) void scan_kernel(
    const float* __restrict__ h0,
    const float* __restrict__ Wh,
    const float* __restrict__ bh,
    float* __restrict__ out,        // (B,S,H): holds P on entry, h_t on exit
    float* __restrict__ hlast)      // (B,H)
{
    extern __shared__ float sm[];
    float* Whs = sm;                 // [512][64]   Wh transposed: Whs[k][jl]
    float* hsd = sm + 512 * 64;      // [4][1024]   h duplicated: hsd[b][2k]=hsd[b][2k+1]=h[b][k]
    float* red = hsd + 4 * 1024;     // [2][8][4][64] double-buffered partials

    const int tid = threadIdx.x;
    const int bg  = blockIdx.x >> 3;     // 0..15
    const int jg  = blockIdx.x & 7;      // 0..7
    const int b0  = bg * BC;
    const int j0  = jg * JC;

    // ---- load Wh slice transposed into SMEM (once) ----
    {
        const int jl = tid >> 2;             // 0..63
        const int kb = (tid & 3) * 128;      // k chunk base
        const float* src = Wh + (size_t)(j0 + jl) * HH + kb;
        for (int kk = 0; kk < 128; kk += 4) {
            float4 v = *(const float4*)(src + kk);
            Whs[(kb + kk + 0) * 64 + jl] = v.x;
            Whs[(kb + kk + 1) * 64 + jl] = v.y;
            Whs[(kb + kk + 2) * 64 + jl] = v.z;
            Whs[(kb + kk + 3) * 64 + jl] = v.w;
        }
    }

    const int w     = tid >> 5;          // warp -> peer slice / k-chunk
    const int lane  = tid & 31;
    const int jl2   = lane * 2;          // packed j pair within slice
    const int kbase = w * 64;

    // h-load mapping within warp: 2 rows (b, b+2) x 16 k-quads
    const int hb = lane >> 4;            // 0/1
    const int k4 = kbase + (lane & 15) * 4;

    // reduce / output mapping: one thread per output element
    const int rb = tid >> 6;             // 0..3
    const int rj = tid & 63;             // 0..63
    const float bias = bh[j0 + rj];
    const size_t obase = (size_t)(b0 + rb) * SS * HH + j0 + rj;

    const int* myflag = &g_flag[bg * NGJ + w];
    int* relflag = &g_flag[bg * NGJ + jg];

    __syncthreads();

    for (int t = 0; t < SS; ++t) {
        const size_t oidx = obase + (size_t)t * HH;
        // prefetch own pre-activation (independent of h_{t-1})
        const float pv = __ldcg(out + oidx);

        // ---- acquire peer slice w, load h chunk, store duplicated ----
        float4 v0, v1;
        if (t == 0) {
            v0 = *(const float4*)(h0 + (size_t)(b0 + hb) * HH + k4);
            v1 = *(const float4*)(h0 + (size_t)(b0 + hb + 2) * HH + k4);
        } else {
            while (ld_acq(myflag) < t) { __nanosleep(32); }
            const float* pb = out + ((size_t)(b0 + hb) * SS + (t - 1)) * HH + k4;
            v0 = __ldcg((const float4*)pb);
            v1 = __ldcg((const float4*)(pb + 2 * (size_t)SS * HH));
        }
        *(float4*)&hsd[hb * 1024 + 2 * k4]           = make_float4(v0.x, v0.x, v0.y, v0.y);
        *(float4*)&hsd[hb * 1024 + 2 * k4 + 4]       = make_float4(v0.z, v0.z, v0.w, v0.w);
        *(float4*)&hsd[(hb + 2) * 1024 + 2 * k4]     = make_float4(v1.x, v1.x, v1.y, v1.y);
        *(float4*)&hsd[(hb + 2) * 1024 + 2 * k4 + 4] = make_float4(v1.z, v1.z, v1.w, v1.w);
        __syncwarp();

        // ---- k-partial GEMM, j packed in pairs (f32x2) ----
        unsigned long long a0 = 0ull, a1 = 0ull, a2 = 0ull, a3 = 0ull;
#pragma unroll
        for (int kk = 0; kk < 64; kk += 2) {
            const int k = kbase + kk;
            const unsigned long long w0 = *(const unsigned long long*)&Whs[k * 64 + jl2];
            const unsigned long long w1 = *(const unsigned long long*)&Whs[(k + 1) * 64 + jl2];
            const unsigned long long h0p = *(const unsigned long long*)&hsd[0 * 1024 + 2 * k];
            const unsigned long long h0q = *(const unsigned long long*)&hsd[0 * 1024 + 2 * k + 2];
            const unsigned long long h1p = *(const unsigned long long*)&hsd[1 * 1024 + 2 * k];
            const unsigned long long h1q = *(const unsigned long long*)&hsd[1 * 1024 + 2 * k + 2];
            const unsigned long long h2p = *(const unsigned long long*)&hsd[2 * 1024 + 2 * k];
            const unsigned long long h2q = *(const unsigned long long*)&hsd[2 * 1024 + 2 * k + 2];
            const unsigned long long h3p = *(const unsigned long long*)&hsd[3 * 1024 + 2 * k];
            const unsigned long long h3q = *(const unsigned long long*)&hsd[3 * 1024 + 2 * k + 2];
            a0 = ffma2(h0p, w0, a0); a0 = ffma2(h0q, w1, a0);
            a1 = ffma2(h1p, w0, a1); a1 = ffma2(h1q, w1, a1);
            a2 = ffma2(h2p, w0, a2); a2 = ffma2(h2q, w1, a2);
            a3 = ffma2(h3p, w0, a3); a3 = ffma2(h3q, w1, a3);
        }

        const int rbuf = (t & 1) * 2048;
        *(unsigned long long*)&red[rbuf + (w * 4 + 0) * 64 + jl2] = a0;
        *(unsigned long long*)&red[rbuf + (w * 4 + 1) * 64 + jl2] = a1;
        *(unsigned long long*)&red[rbuf + (w * 4 + 2) * 64 + jl2] = a2;
        *(unsigned long long*)&red[rbuf + (w * 4 + 3) * 64 + jl2] = a3;
        __syncthreads();

        // ---- reduce, add P + bias, tanh, write h_t ----
        float sum = pv + bias;
#pragma unroll
        for (int ww = 0; ww < 8; ++ww)
            sum += red[rbuf + (ww * 4 + rb) * 64 + rj];
        const float hnew = tanhf(sum);
        __stcg(out + oidx, hnew);
        if (t == SS - 1)
            hlast[(size_t)(b0 + rb) * HH + j0 + rj] = hnew;

        // ---- release own slice for step t ----
        if (t < SS - 1) {
            __threadfence();
            __syncthreads();
            if (tid == 0) st_rel(relflag, t + 1);
        }
    }
}

// ---------------------------------------------------------------------------
extern "C" void kernel_launch(void* const* d_in, const int* in_sizes, int n_in,
                              void* d_out, int out_size) {
    const float* x   = (const float*)d_in[0];   // (B,S,I)
    const float* h0  = (const float*)d_in[1];   // (B,H)
    const float* Wx  = (const float*)d_in[2];   // (H,I)
    const float* Wh  = (const float*)d_in[3];   // (H,H)
    const float* bh  = (const float*)d_in[4];   // (H,)
    float* out   = (float*)d_out;                          // (B,S,H)
    float* hlast = out + (size_t)BB * SS * HH;             // (B,H)

    cudaFuncSetAttribute(scan_kernel,
                         cudaFuncAttributeMaxDynamicSharedMemorySize, SCAN_SMEM);

    reset_kernel<<<1, 128>>>();

    dim3 gg((BB * SS) / 64, HH / 64);   // (2048, 8)
    xproj_kernel<<<gg, 256>>>(x, Wx, out);

    scan_kernel<<<128, 256, SCAN_SMEM>>>(h0, Wh, bh, out, hlast);
}